// round 3
// baseline (speedup 1.0000x reference)
#include <cuda_runtime.h>
#include <math.h>

#define S_LEN   2048
#define D_MODEL 2048
#define NH      16
#define DH      128
#define BATCH   2
#define TOKENS  (BATCH * S_LEN)   // 4096

// ---------------- scratch (device globals: allocation-free) ----------------
__device__ float g_Q[TOKENS * D_MODEL];
__device__ float g_K[TOKENS * D_MODEL];
__device__ float g_V[TOKENS * D_MODEL];
__device__ float g_O[TOKENS * D_MODEL];

// ---------------- SGEMM: C[4096,2048] = A[4096,2048] @ B[2048,2048] --------
#define GBM 128
#define GBN 128
#define GBK 16
#define AS_STRIDE 132   // padded stage for A (transposed store, ~2-way conflicts)

__global__ void __launch_bounds__(256, 2) sgemm_kernel(
    const float* __restrict__ A, const float* __restrict__ B, float* __restrict__ C)
{
    const int M = TOKENS, N = D_MODEL, K = D_MODEL;
    (void)M;
    __shared__ float As[GBK * AS_STRIDE];
    __shared__ float Bs[GBK * GBN];

    const int tid  = threadIdx.x;
    const int brow = blockIdx.y, bcol = blockIdx.x;

    const int aRow = tid >> 2;          // 0..63
    const int aCol = (tid & 3) << 2;    // 0,4,8,12
    const int bRow = tid >> 5;          // 0..7
    const int bCol = (tid & 31) << 2;   // 0..124

    const int tRow = (tid >> 4) << 3;   // 0..120
    const int tCol = (tid & 15) << 3;   // 0..120

    const float* Ag = A + (size_t)brow * GBM * K;
    const float* Bg = B + bcol * GBN;

    float acc[8][8];
    #pragma unroll
    for (int i = 0; i < 8; i++)
        #pragma unroll
        for (int j = 0; j < 8; j++) acc[i][j] = 0.0f;

    for (int k0 = 0; k0 < K; k0 += GBK) {
        #pragma unroll
        for (int i = 0; i < 2; i++) {
            float4 v = *(const float4*)(Ag + (size_t)(aRow + i * 64) * K + k0 + aCol);
            As[(aCol + 0) * AS_STRIDE + aRow + i * 64] = v.x;
            As[(aCol + 1) * AS_STRIDE + aRow + i * 64] = v.y;
            As[(aCol + 2) * AS_STRIDE + aRow + i * 64] = v.z;
            As[(aCol + 3) * AS_STRIDE + aRow + i * 64] = v.w;
        }
        #pragma unroll
        for (int i = 0; i < 2; i++) {
            *(float4*)&Bs[(bRow + i * 8) * GBN + bCol] =
                *(const float4*)(Bg + (size_t)(k0 + bRow + i * 8) * N + bCol);
        }
        __syncthreads();

        #pragma unroll
        for (int k = 0; k < GBK; k++) {
            float ra[8], rb[8];
            *(float4*)&ra[0] = *(const float4*)&As[k * AS_STRIDE + tRow];
            *(float4*)&ra[4] = *(const float4*)&As[k * AS_STRIDE + tRow + 4];
            *(float4*)&rb[0] = *(const float4*)&Bs[k * GBN + tCol];
            *(float4*)&rb[4] = *(const float4*)&Bs[k * GBN + tCol + 4];
            #pragma unroll
            for (int i = 0; i < 8; i++)
                #pragma unroll
                for (int j = 0; j < 8; j++)
                    acc[i][j] += ra[i] * rb[j];
        }
        __syncthreads();
    }

    float* Cg = C + (size_t)(brow * GBM + tRow) * N + bcol * GBN + tCol;
    #pragma unroll
    for (int i = 0; i < 8; i++) {
        *(float4*)&Cg[(size_t)i * N + 0] = make_float4(acc[i][0], acc[i][1], acc[i][2], acc[i][3]);
        *(float4*)&Cg[(size_t)i * N + 4] = make_float4(acc[i][4], acc[i][5], acc[i][6], acc[i][7]);
    }
}

// ---------------- RoPE (in-place), optional extra scale --------------------
__global__ void rope_kernel(float* __restrict__ X, float scale)
{
    int idx = blockIdx.x * blockDim.x + threadIdx.x;
    if (idx >= TOKENS * NH * 64) return;
    int i  = idx & 63;
    int hh = (idx >> 6) & (NH - 1);
    int t  = idx >> 10;                 // token 0..4095
    int pos = t & (S_LEN - 1);          // position = arange(S) per batch

    // inv_freq = 10000^{-2i/128}; phase in double to dominate jax's own fp32 rounding
    double inv = exp(-((double)(2 * i) / 128.0) * 9.210340371976184); // ln(10000)
    double f   = (double)pos * inv;
    float c = (float)cos(f);
    float s = (float)sin(f);

    float* p = X + (size_t)t * D_MODEL + hh * DH;
    float x1 = p[i];
    float x2 = p[i + 64];
    p[i]      = (x1 * c - x2 * s) * scale;
    p[i + 64] = (x2 * c + x1 * s) * scale;
}

// ---------------- Flash attention (fp32, causal) ---------------------------
#define BQ 64
#define BKV 64
#define QS_STRIDE 72     // [dh][row] transposed stage, float4-aligned
#define VS_STRIDE 132    // [row][dh] natural stage
#define PS_STRIDE 65     // padded prob tile
#define ATTN_SMEM ((128 * QS_STRIDE + 128 * QS_STRIDE + BKV * VS_STRIDE + BQ * PS_STRIDE) * 4)

__global__ void __launch_bounds__(256) attn_kernel(
    const float* __restrict__ Q, const float* __restrict__ K,
    const float* __restrict__ V, float* __restrict__ O)
{
    const int b  = blockIdx.z;
    const int h  = blockIdx.y;
    const int qb = blockIdx.x;
    const int tid = threadIdx.x;
    const int ty = tid >> 4;       // 0..15
    const int tx = tid & 15;       // 0..15
    const int r0 = ty * 4;         // 4 q-rows per thread
    const int c0 = tx * 4;         // 4 k-cols per thread (scores)
    const int d0 = tx * 8;         // 8 out-dims per thread (PV)

    extern __shared__ float sm[];
    float* Qs = sm;                              // [128][QS_STRIDE] transposed
    float* Ks = Qs + 128 * QS_STRIDE;            // [128][QS_STRIDE] transposed
    float* Vs = Ks + 128 * QS_STRIDE;            // [BKV][VS_STRIDE]
    float* Ps = Vs + BKV * VS_STRIDE;            // [BQ][PS_STRIDE]

    const size_t base = ((size_t)b * S_LEN) * D_MODEL + (size_t)h * DH;
    const float* Qg = Q + base + (size_t)(qb * BQ) * D_MODEL;

    // Load Q tile transposed (Q already pre-scaled by 1/sqrt(DH) in rope)
    for (int i = tid; i < BQ * (DH / 4); i += 256) {
        int r = i >> 5;
        int d = (i & 31) << 2;
        float4 v = *(const float4*)(Qg + (size_t)r * D_MODEL + d);
        Qs[(d + 0) * QS_STRIDE + r] = v.x;
        Qs[(d + 1) * QS_STRIDE + r] = v.y;
        Qs[(d + 2) * QS_STRIDE + r] = v.z;
        Qs[(d + 3) * QS_STRIDE + r] = v.w;
    }

    float m[4], l[4], o[4][8];
    #pragma unroll
    for (int i = 0; i < 4; i++) {
        m[i] = -INFINITY; l[i] = 0.0f;
        #pragma unroll
        for (int j = 0; j < 8; j++) o[i][j] = 0.0f;
    }

    for (int kb = 0; kb <= qb; kb++) {
        const float* Kg = K + base + (size_t)(kb * BKV) * D_MODEL;
        const float* Vg = V + base + (size_t)(kb * BKV) * D_MODEL;

        __syncthreads();   // previous PV readers done before overwriting K/V
        for (int i = tid; i < BKV * (DH / 4); i += 256) {
            int r = i >> 5;
            int d = (i & 31) << 2;
            float4 kv = *(const float4*)(Kg + (size_t)r * D_MODEL + d);
            Ks[(d + 0) * QS_STRIDE + r] = kv.x;
            Ks[(d + 1) * QS_STRIDE + r] = kv.y;
            Ks[(d + 2) * QS_STRIDE + r] = kv.z;
            Ks[(d + 3) * QS_STRIDE + r] = kv.w;
            float4 vv = *(const float4*)(Vg + (size_t)r * D_MODEL + d);
            *(float4*)&Vs[r * VS_STRIDE + d] = vv;
        }
        __syncthreads();

        // S = Q K^T (tile), thread computes 4x4
        float s[4][4];
        #pragma unroll
        for (int i = 0; i < 4; i++)
            #pragma unroll
            for (int j = 0; j < 4; j++) s[i][j] = 0.0f;

        #pragma unroll 4
        for (int k = 0; k < DH; k++) {
            float4 a4 = *(const float4*)&Qs[k * QS_STRIDE + r0];
            float4 b4 = *(const float4*)&Ks[k * QS_STRIDE + c0];
            float ra[4] = {a4.x, a4.y, a4.z, a4.w};
            float rb[4] = {b4.x, b4.y, b4.z, b4.w};
            #pragma unroll
            for (int i = 0; i < 4; i++)
                #pragma unroll
                for (int j = 0; j < 4; j++)
                    s[i][j] += ra[i] * rb[j];
        }

        if (kb == qb) {   // causal mask only touches the diagonal block
            #pragma unroll
            for (int i = 0; i < 4; i++)
                #pragma unroll
                for (int j = 0; j < 4; j++)
                    if (c0 + j > r0 + i) s[i][j] = -INFINITY;
        }

        // online softmax over the 64-wide tile (row reduce across 16 tx lanes)
        float rmax[4];
        #pragma unroll
        for (int i = 0; i < 4; i++)
            rmax[i] = fmaxf(fmaxf(s[i][0], s[i][1]), fmaxf(s[i][2], s[i][3]));
        #pragma unroll
        for (int i = 0; i < 4; i++) {
            #pragma unroll
            for (int off = 8; off > 0; off >>= 1)
                rmax[i] = fmaxf(rmax[i], __shfl_xor_sync(0xffffffffu, rmax[i], off));
        }

        #pragma unroll
        for (int i = 0; i < 4; i++) {
            float mn = fmaxf(m[i], rmax[i]);
            float al = (m[i] == -INFINITY) ? 0.0f : __expf(m[i] - mn);
            float rsum = 0.0f;
            #pragma unroll
            for (int j = 0; j < 4; j++) {
                float p = __expf(s[i][j] - mn);   // exp(-inf)=0 handles mask
                Ps[(r0 + i) * PS_STRIDE + c0 + j] = p;
                rsum += p;
            }
            #pragma unroll
            for (int off = 8; off > 0; off >>= 1)
                rsum += __shfl_xor_sync(0xffffffffu, rsum, off);
            l[i] = l[i] * al + rsum;
            m[i] = mn;
            #pragma unroll
            for (int j = 0; j < 8; j++) o[i][j] *= al;
        }
        __syncthreads();

        // O += P V  (thread: 4 rows x 8 dims)
        #pragma unroll 4
        for (int c = 0; c < BKV; c++) {
            float4 v0 = *(const float4*)&Vs[c * VS_STRIDE + d0];
            float4 v1 = *(const float4*)&Vs[c * VS_STRIDE + d0 + 4];
            float pi[4];
            #pragma unroll
            for (int i = 0; i < 4; i++) pi[i] = Ps[(r0 + i) * PS_STRIDE + c];
            #pragma unroll
            for (int i = 0; i < 4; i++) {
                o[i][0] += pi[i] * v0.x; o[i][1] += pi[i] * v0.y;
                o[i][2] += pi[i] * v0.z; o[i][3] += pi[i] * v0.w;
                o[i][4] += pi[i] * v1.x; o[i][5] += pi[i] * v1.y;
                o[i][6] += pi[i] * v1.z; o[i][7] += pi[i] * v1.w;
            }
        }
    }

    float* Og = O + base + (size_t)(qb * BQ) * D_MODEL;
    #pragma unroll
    for (int i = 0; i < 4; i++) {
        float inv = 1.0f / l[i];
        float* dst = Og + (size_t)(r0 + i) * D_MODEL + d0;
        *(float4*)dst       = make_float4(o[i][0]*inv, o[i][1]*inv, o[i][2]*inv, o[i][3]*inv);
        *(float4*)(dst + 4) = make_float4(o[i][4]*inv, o[i][5]*inv, o[i][6]*inv, o[i][7]*inv);
    }
}

// ---------------- launch ----------------------------------------------------
extern "C" void kernel_launch(void* const* d_in, const int* in_sizes, int n_in,
                              void* d_out, int out_size)
{
    (void)in_sizes; (void)n_in; (void)out_size;
    const float* hidden = (const float*)d_in[0];
    // d_in[1] = mask (always tril), d_in[2] = position (always arange): unused
    const float* Wq = (const float*)d_in[3];
    const float* Wk = (const float*)d_in[4];
    const float* Wv = (const float*)d_in[5];
    const float* Wo = (const float*)d_in[6];
    float* out = (float*)d_out;

    float *Qp, *Kp, *Vp, *Op;
    cudaGetSymbolAddress((void**)&Qp, g_Q);
    cudaGetSymbolAddress((void**)&Kp, g_K);
    cudaGetSymbolAddress((void**)&Vp, g_V);
    cudaGetSymbolAddress((void**)&Op, g_O);

    dim3 ggrid(D_MODEL / GBN, TOKENS / GBM);
    sgemm_kernel<<<ggrid, 256>>>(hidden, Wq, Qp);
    sgemm_kernel<<<ggrid, 256>>>(hidden, Wk, Kp);
    sgemm_kernel<<<ggrid, 256>>>(hidden, Wv, Vp);

    int nrope = TOKENS * NH * 64;
    rope_kernel<<<(nrope + 255) / 256, 256>>>(Qp, 0.08838834764831845f); // 1/sqrt(128)
    rope_kernel<<<(nrope + 255) / 256, 256>>>(Kp, 1.0f);

    cudaFuncSetAttribute(attn_kernel, cudaFuncAttributeMaxDynamicSharedMemorySize, ATTN_SMEM);
    attn_kernel<<<dim3(S_LEN / BQ, NH, BATCH), 256, ATTN_SMEM>>>(Qp, Kp, Vp, Op);

    sgemm_kernel<<<ggrid, 256>>>(Op, Wo, out);
}

// round 7
// speedup vs baseline: 1.7291x; 1.7291x over previous
#include <cuda_runtime.h>
#include <cuda_bf16.h>
#include <cstdint>
#include <math.h>

#define S_LEN   2048
#define D_MODEL 2048
#define NH      16
#define DH      128
#define BATCH   2
#define TOKENS  (BATCH * S_LEN)   // 4096

// ---------------- scratch (device globals: allocation-free) ----------------
__device__ float g_Q[TOKENS * D_MODEL];
__device__ float g_K[TOKENS * D_MODEL];
__device__ float g_V[TOKENS * D_MODEL];
__device__ float g_O[TOKENS * D_MODEL];
__device__ __nv_bfloat16 g_Ah[TOKENS * D_MODEL];     // split A (hi)
__device__ __nv_bfloat16 g_Al[TOKENS * D_MODEL];     // split A (lo)
__device__ __nv_bfloat16 g_Bh[D_MODEL * D_MODEL];    // split+transposed W (hi) [N][K]
__device__ __nv_bfloat16 g_Bl[D_MODEL * D_MODEL];    // split+transposed W (lo) [N][K]
__device__ float2 g_cs[S_LEN * 64];                  // rope cos/sin table

// ---------------- rope table (fp64 once, tiny) -----------------------------
__global__ void rope_table_kernel()
{
    int idx = blockIdx.x * blockDim.x + threadIdx.x;
    if (idx >= S_LEN * 64) return;
    int pos = idx >> 6;
    int i   = idx & 63;
    double inv = exp(-((double)(2 * i) / 128.0) * 9.210340371976184); // ln(10000)
    double f   = (double)pos * inv;
    g_cs[idx] = make_float2((float)cos(f), (float)sin(f));
}

// ---------------- split fp32 -> bf16 hi/lo ---------------------------------
__global__ void split_kernel(const float* __restrict__ x,
                             __nv_bfloat16* __restrict__ hi,
                             __nv_bfloat16* __restrict__ lo, int n2)
{
    int i = blockIdx.x * blockDim.x + threadIdx.x;   // per float2
    if (i >= n2) return;
    float2 v = ((const float2*)x)[i];
    __nv_bfloat16 h0 = __float2bfloat16(v.x);
    __nv_bfloat16 h1 = __float2bfloat16(v.y);
    __nv_bfloat16 l0 = __float2bfloat16(v.x - __bfloat162float(h0));
    __nv_bfloat16 l1 = __float2bfloat16(v.y - __bfloat162float(h1));
    ((__nv_bfloat162*)hi)[i] = __halves2bfloat162(h0, h1);
    ((__nv_bfloat162*)lo)[i] = __halves2bfloat162(l0, l1);
}

// ---------------- transpose + split: W[K][N] -> BT[N][K] bf16 hi/lo --------
__global__ void tsplit_kernel(const float* __restrict__ W,
                              __nv_bfloat16* __restrict__ hiT,
                              __nv_bfloat16* __restrict__ loT)
{
    __shared__ float tile[32][33];
    int tx = threadIdx.x, ty = threadIdx.y;          // 32 x 8
    int x0 = blockIdx.x * 32, y0 = blockIdx.y * 32;
    #pragma unroll
    for (int j = 0; j < 32; j += 8)
        tile[ty + j][tx] = W[(size_t)(y0 + ty + j) * D_MODEL + x0 + tx];
    __syncthreads();
    #pragma unroll
    for (int j = 0; j < 32; j += 8) {
        float v = tile[tx][ty + j];
        __nv_bfloat16 h = __float2bfloat16(v);
        __nv_bfloat16 l = __float2bfloat16(v - __bfloat162float(h));
        size_t o = (size_t)(x0 + ty + j) * D_MODEL + y0 + tx;
        hiT[o] = h;
        loT[o] = l;
    }
}

// ---------------- bf16x3 tensor-core GEMM ----------------------------------
// C[M,N] = A[M,K] @ B[K,N], A given as hi/lo bf16 [M,K], B given as hi/lo
// bf16 TRANSPOSED [N,K]. M=4096, N=K=2048. fp32 accumulate.
#define TBM 128
#define TBN 128
#define TBK 32
#define TS  40    // smem row stride in halves (padded: conflict-free frags)

#define MMA16816(d, a, b)                                                     \
    asm volatile(                                                             \
        "mma.sync.aligned.m16n8k16.row.col.f32.bf16.bf16.f32 "                \
        "{%0,%1,%2,%3},{%4,%5,%6,%7},{%8,%9},{%0,%1,%2,%3};\n"                \
        : "+f"(d[0]), "+f"(d[1]), "+f"(d[2]), "+f"(d[3])                      \
        : "r"(a[0]), "r"(a[1]), "r"(a[2]), "r"(a[3]), "r"(b[0]), "r"(b[1]))

__global__ void __launch_bounds__(256, 2) gemm_bf16x3_kernel(
    const __nv_bfloat16* __restrict__ Ah, const __nv_bfloat16* __restrict__ Al,
    const __nv_bfloat16* __restrict__ BTh, const __nv_bfloat16* __restrict__ BTl,
    float* __restrict__ C)
{
    const int K = D_MODEL, N = D_MODEL;
    __shared__ __align__(16) __nv_bfloat16 sAh[TBM * TS];
    __shared__ __align__(16) __nv_bfloat16 sAl[TBM * TS];
    __shared__ __align__(16) __nv_bfloat16 sBh[TBN * TS];
    __shared__ __align__(16) __nv_bfloat16 sBl[TBN * TS];

    const int t = threadIdx.x;
    const int bm = blockIdx.y, bn = blockIdx.x;
    const int warp = t >> 5, lane = t & 31;
    const int wm = warp >> 2;      // 0..1  (64 rows each)
    const int wn = warp & 3;       // 0..3  (32 cols each)
    const int g  = lane >> 2;      // group 0..7
    const int tq = lane & 3;       // thread-in-group

    float acc[4][4][4];
    #pragma unroll
    for (int a = 0; a < 4; a++)
        #pragma unroll
        for (int b = 0; b < 4; b++)
            #pragma unroll
            for (int c = 0; c < 4; c++) acc[a][b][c] = 0.0f;

    for (int k0 = 0; k0 < K; k0 += TBK) {
        __syncthreads();
        #pragma unroll
        for (int rep = 0; rep < 2; rep++) {
            int idx = t + rep * 256;          // 0..511
            int r = idx >> 2;                 // 0..127
            int c = (idx & 3) * 8;            // 0,8,16,24
            size_t ga = (size_t)(bm * TBM + r) * K + k0 + c;
            size_t gb = (size_t)(bn * TBN + r) * K + k0 + c;
            *(uint4*)&sAh[r * TS + c] = *(const uint4*)(Ah + ga);
            *(uint4*)&sAl[r * TS + c] = *(const uint4*)(Al + ga);
            *(uint4*)&sBh[r * TS + c] = *(const uint4*)(BTh + gb);
            *(uint4*)&sBl[r * TS + c] = *(const uint4*)(BTl + gb);
        }
        __syncthreads();

        #pragma unroll
        for (int ks = 0; ks < TBK; ks += 16) {
            uint32_t fah[4][4], fal[4][4], fbh[4][2], fbl[4][2];
            #pragma unroll
            for (int mf = 0; mf < 4; mf++) {
                int base = (wm * 64 + mf * 16 + g) * TS + ks + tq * 2;
                fah[mf][0] = *(const uint32_t*)&sAh[base];
                fah[mf][1] = *(const uint32_t*)&sAh[base + 8 * TS];
                fah[mf][2] = *(const uint32_t*)&sAh[base + 8];
                fah[mf][3] = *(const uint32_t*)&sAh[base + 8 * TS + 8];
                fal[mf][0] = *(const uint32_t*)&sAl[base];
                fal[mf][1] = *(const uint32_t*)&sAl[base + 8 * TS];
                fal[mf][2] = *(const uint32_t*)&sAl[base + 8];
                fal[mf][3] = *(const uint32_t*)&sAl[base + 8 * TS + 8];
            }
            #pragma unroll
            for (int nf = 0; nf < 4; nf++) {
                int base = (wn * 32 + nf * 8 + g) * TS + ks + tq * 2;
                fbh[nf][0] = *(const uint32_t*)&sBh[base];
                fbh[nf][1] = *(const uint32_t*)&sBh[base + 8];
                fbl[nf][0] = *(const uint32_t*)&sBl[base];
                fbl[nf][1] = *(const uint32_t*)&sBl[base + 8];
            }
            #pragma unroll
            for (int mf = 0; mf < 4; mf++)
                #pragma unroll
                for (int nf = 0; nf < 4; nf++) {
                    MMA16816(acc[mf][nf], fah[mf], fbh[nf]);
                    MMA16816(acc[mf][nf], fah[mf], fbl[nf]);
                    MMA16816(acc[mf][nf], fal[mf], fbh[nf]);
                }
        }
    }

    #pragma unroll
    for (int mf = 0; mf < 4; mf++) {
        int row = bm * TBM + wm * 64 + mf * 16 + g;
        #pragma unroll
        for (int nf = 0; nf < 4; nf++) {
            int col = bn * TBN + wn * 32 + nf * 8 + tq * 2;
            *(float2*)&C[(size_t)row * N + col] =
                make_float2(acc[mf][nf][0], acc[mf][nf][1]);
            *(float2*)&C[(size_t)(row + 8) * N + col] =
                make_float2(acc[mf][nf][2], acc[mf][nf][3]);
        }
    }
}

// ---------------- RoPE (table-based, in-place), optional extra scale -------
__global__ void rope_kernel(float* __restrict__ X, float scale)
{
    int idx = blockIdx.x * blockDim.x + threadIdx.x;
    if (idx >= TOKENS * NH * 64) return;
    int i  = idx & 63;
    int hh = (idx >> 6) & (NH - 1);
    int t  = idx >> 10;                 // token 0..4095
    int pos = t & (S_LEN - 1);

    float2 cs = g_cs[pos * 64 + i];
    float c = cs.x, s = cs.y;

    float* p = X + (size_t)t * D_MODEL + hh * DH;
    float x1 = p[i];
    float x2 = p[i + 64];
    p[i]      = (x1 * c - x2 * s) * scale;
    p[i + 64] = (x2 * c + x1 * s) * scale;
}

// ---------------- Flash attention (fp32, causal) ---------------------------
#define BQ 64
#define BKV 64
#define QS_STRIDE 72
#define VS_STRIDE 132
#define PS_STRIDE 65
#define ATTN_SMEM ((128 * QS_STRIDE + 128 * QS_STRIDE + BKV * VS_STRIDE + BQ * PS_STRIDE) * 4)

__global__ void __launch_bounds__(256) attn_kernel(
    const float* __restrict__ Q, const float* __restrict__ K,
    const float* __restrict__ V, float* __restrict__ O)
{
    const int b  = blockIdx.z;
    const int h  = blockIdx.y;
    const int qb = blockIdx.x;
    const int tid = threadIdx.x;
    const int ty = tid >> 4;
    const int tx = tid & 15;
    const int r0 = ty * 4;
    const int c0 = tx * 4;
    const int d0 = tx * 8;

    extern __shared__ float sm[];
    float* Qs = sm;
    float* Ks = Qs + 128 * QS_STRIDE;
    float* Vs = Ks + 128 * QS_STRIDE;
    float* Ps = Vs + BKV * VS_STRIDE;

    const size_t base = ((size_t)b * S_LEN) * D_MODEL + (size_t)h * DH;
    const float* Qg = Q + base + (size_t)(qb * BQ) * D_MODEL;

    for (int i = tid; i < BQ * (DH / 4); i += 256) {
        int r = i >> 5;
        int d = (i & 31) << 2;
        float4 v = *(const float4*)(Qg + (size_t)r * D_MODEL + d);
        Qs[(d + 0) * QS_STRIDE + r] = v.x;
        Qs[(d + 1) * QS_STRIDE + r] = v.y;
        Qs[(d + 2) * QS_STRIDE + r] = v.z;
        Qs[(d + 3) * QS_STRIDE + r] = v.w;
    }

    float m[4], l[4], o[4][8];
    #pragma unroll
    for (int i = 0; i < 4; i++) {
        m[i] = -INFINITY; l[i] = 0.0f;
        #pragma unroll
        for (int j = 0; j < 8; j++) o[i][j] = 0.0f;
    }

    for (int kb = 0; kb <= qb; kb++) {
        const float* Kg = K + base + (size_t)(kb * BKV) * D_MODEL;
        const float* Vg = V + base + (size_t)(kb * BKV) * D_MODEL;

        __syncthreads();
        for (int i = tid; i < BKV * (DH / 4); i += 256) {
            int r = i >> 5;
            int d = (i & 31) << 2;
            float4 kv = *(const float4*)(Kg + (size_t)r * D_MODEL + d);
            Ks[(d + 0) * QS_STRIDE + r] = kv.x;
            Ks[(d + 1) * QS_STRIDE + r] = kv.y;
            Ks[(d + 2) * QS_STRIDE + r] = kv.z;
            Ks[(d + 3) * QS_STRIDE + r] = kv.w;
            float4 vv = *(const float4*)(Vg + (size_t)r * D_MODEL + d);
            *(float4*)&Vs[r * VS_STRIDE + d] = vv;
        }
        __syncthreads();

        float s[4][4];
        #pragma unroll
        for (int i = 0; i < 4; i++)
            #pragma unroll
            for (int j = 0; j < 4; j++) s[i][j] = 0.0f;

        #pragma unroll 4
        for (int k = 0; k < DH; k++) {
            float4 a4 = *(const float4*)&Qs[k * QS_STRIDE + r0];
            float4 b4 = *(const float4*)&Ks[k * QS_STRIDE + c0];
            float ra[4] = {a4.x, a4.y, a4.z, a4.w};
            float rb[4] = {b4.x, b4.y, b4.z, b4.w};
            #pragma unroll
            for (int i = 0; i < 4; i++)
                #pragma unroll
                for (int j = 0; j < 4; j++)
                    s[i][j] += ra[i] * rb[j];
        }

        if (kb == qb) {
            #pragma unroll
            for (int i = 0; i < 4; i++)
                #pragma unroll
                for (int j = 0; j < 4; j++)
                    if (c0 + j > r0 + i) s[i][j] = -INFINITY;
        }

        float rmax[4];
        #pragma unroll
        for (int i = 0; i < 4; i++)
            rmax[i] = fmaxf(fmaxf(s[i][0], s[i][1]), fmaxf(s[i][2], s[i][3]));
        #pragma unroll
        for (int i = 0; i < 4; i++) {
            #pragma unroll
            for (int off = 8; off > 0; off >>= 1)
                rmax[i] = fmaxf(rmax[i], __shfl_xor_sync(0xffffffffu, rmax[i], off));
        }

        #pragma unroll
        for (int i = 0; i < 4; i++) {
            float mn = fmaxf(m[i], rmax[i]);
            float al = (m[i] == -INFINITY) ? 0.0f : __expf(m[i] - mn);
            float rsum = 0.0f;
            #pragma unroll
            for (int j = 0; j < 4; j++) {
                float p = __expf(s[i][j] - mn);
                Ps[(r0 + i) * PS_STRIDE + c0 + j] = p;
                rsum += p;
            }
            #pragma unroll
            for (int off = 8; off > 0; off >>= 1)
                rsum += __shfl_xor_sync(0xffffffffu, rsum, off);
            l[i] = l[i] * al + rsum;
            m[i] = mn;
            #pragma unroll
            for (int j = 0; j < 8; j++) o[i][j] *= al;
        }
        __syncthreads();

        #pragma unroll 4
        for (int c = 0; c < BKV; c++) {
            float4 v0 = *(const float4*)&Vs[c * VS_STRIDE + d0];
            float4 v1 = *(const float4*)&Vs[c * VS_STRIDE + d0 + 4];
            float pi[4];
            #pragma unroll
            for (int i = 0; i < 4; i++) pi[i] = Ps[(r0 + i) * PS_STRIDE + c];
            #pragma unroll
            for (int i = 0; i < 4; i++) {
                o[i][0] += pi[i] * v0.x; o[i][1] += pi[i] * v0.y;
                o[i][2] += pi[i] * v0.z; o[i][3] += pi[i] * v0.w;
                o[i][4] += pi[i] * v1.x; o[i][5] += pi[i] * v1.y;
                o[i][6] += pi[i] * v1.z; o[i][7] += pi[i] * v1.w;
            }
        }
    }

    float* Og = O + base + (size_t)(qb * BQ) * D_MODEL;
    #pragma unroll
    for (int i = 0; i < 4; i++) {
        float inv = 1.0f / l[i];
        float* dst = Og + (size_t)(r0 + i) * D_MODEL + d0;
        *(float4*)dst       = make_float4(o[i][0]*inv, o[i][1]*inv, o[i][2]*inv, o[i][3]*inv);
        *(float4*)(dst + 4) = make_float4(o[i][4]*inv, o[i][5]*inv, o[i][6]*inv, o[i][7]*inv);
    }
}

// ---------------- launch ----------------------------------------------------
extern "C" void kernel_launch(void* const* d_in, const int* in_sizes, int n_in,
                              void* d_out, int out_size)
{
    (void)in_sizes; (void)n_in; (void)out_size;
    const float* hidden = (const float*)d_in[0];
    const float* Wq = (const float*)d_in[3];
    const float* Wk = (const float*)d_in[4];
    const float* Wv = (const float*)d_in[5];
    const float* Wo = (const float*)d_in[6];
    float* out = (float*)d_out;

    float *Qp, *Kp, *Vp, *Op;
    __nv_bfloat16 *Ahp, *Alp, *Bhp, *Blp;
    cudaGetSymbolAddress((void**)&Qp, g_Q);
    cudaGetSymbolAddress((void**)&Kp, g_K);
    cudaGetSymbolAddress((void**)&Vp, g_V);
    cudaGetSymbolAddress((void**)&Op, g_O);
    cudaGetSymbolAddress((void**)&Ahp, g_Ah);
    cudaGetSymbolAddress((void**)&Alp, g_Al);
    cudaGetSymbolAddress((void**)&Bhp, g_Bh);
    cudaGetSymbolAddress((void**)&Blp, g_Bl);

    // rope table
    rope_table_kernel<<<(S_LEN * 64 + 255) / 256, 256>>>();

    // split hidden (A side for QKV projections)
    int n2 = TOKENS * D_MODEL / 2;
    split_kernel<<<(n2 + 255) / 256, 256>>>(hidden, Ahp, Alp, n2);

    dim3 tgrid(D_MODEL / 32, D_MODEL / 32);
    dim3 tblk(32, 8);
    dim3 ggrid(D_MODEL / TBN, TOKENS / TBM);

    tsplit_kernel<<<tgrid, tblk>>>(Wq, Bhp, Blp);
    gemm_bf16x3_kernel<<<ggrid, 256>>>(Ahp, Alp, Bhp, Blp, Qp);
    tsplit_kernel<<<tgrid, tblk>>>(Wk, Bhp, Blp);
    gemm_bf16x3_kernel<<<ggrid, 256>>>(Ahp, Alp, Bhp, Blp, Kp);
    tsplit_kernel<<<tgrid, tblk>>>(Wv, Bhp, Blp);
    gemm_bf16x3_kernel<<<ggrid, 256>>>(Ahp, Alp, Bhp, Blp, Vp);

    int nrope = TOKENS * NH * 64;
    rope_kernel<<<(nrope + 255) / 256, 256>>>(Qp, 0.08838834764831845f); // 1/sqrt(128)
    rope_kernel<<<(nrope + 255) / 256, 256>>>(Kp, 1.0f);

    cudaFuncSetAttribute(attn_kernel, cudaFuncAttributeMaxDynamicSharedMemorySize, ATTN_SMEM);
    attn_kernel<<<dim3(S_LEN / BQ, NH, BATCH), 256, ATTN_SMEM>>>(Qp, Kp, Vp, Op);

    // output projection
    split_kernel<<<(n2 + 255) / 256, 256>>>(Op, Ahp, Alp, n2);
    tsplit_kernel<<<tgrid, tblk>>>(Wo, Bhp, Blp);
    gemm_bf16x3_kernel<<<ggrid, 256>>>(Ahp, Alp, Bhp, Blp, out);
}

// round 8
// speedup vs baseline: 2.3630x; 1.3666x over previous
#include <cuda_runtime.h>
#include <cuda_bf16.h>
#include <cstdint>
#include <math.h>

#define S_LEN   2048
#define D_MODEL 2048
#define NH      16
#define DH      128
#define BATCH   2
#define TOKENS  (BATCH * S_LEN)   // 4096

// ---------------- scratch (device globals: allocation-free) ----------------
__device__ float g_Q[TOKENS * D_MODEL];
__device__ float g_K[TOKENS * D_MODEL];
__device__ float g_V[TOKENS * D_MODEL];
__device__ float g_O[TOKENS * D_MODEL];
__device__ __nv_bfloat16 g_Ah[TOKENS * D_MODEL];
__device__ __nv_bfloat16 g_Al[TOKENS * D_MODEL];
__device__ __nv_bfloat16 g_Bh[D_MODEL * D_MODEL];
__device__ __nv_bfloat16 g_Bl[D_MODEL * D_MODEL];
__device__ __nv_bfloat16 g_Qh[TOKENS * D_MODEL];
__device__ __nv_bfloat16 g_Ql[TOKENS * D_MODEL];
__device__ __nv_bfloat16 g_Kh[TOKENS * D_MODEL];
__device__ __nv_bfloat16 g_Kl[TOKENS * D_MODEL];
__device__ __nv_bfloat16 g_Vh[TOKENS * D_MODEL];
__device__ __nv_bfloat16 g_Vl[TOKENS * D_MODEL];
__device__ float2 g_cs[S_LEN * 64];

// ---------------- common asm helpers ---------------------------------------
#define MMA16816(d, a, b)                                                     \
    asm volatile(                                                             \
        "mma.sync.aligned.m16n8k16.row.col.f32.bf16.bf16.f32 "                \
        "{%0,%1,%2,%3},{%4,%5,%6,%7},{%8,%9},{%0,%1,%2,%3};\n"                \
        : "+f"(d[0]), "+f"(d[1]), "+f"(d[2]), "+f"(d[3])                      \
        : "r"(a[0]), "r"(a[1]), "r"(a[2]), "r"(a[3]), "r"(b[0]), "r"(b[1]))

#define LDSM_X4(d0, d1, d2, d3, addr)                                         \
    asm volatile("ldmatrix.sync.aligned.m8n8.x4.shared.b16 {%0,%1,%2,%3}, [%4];" \
                 : "=r"(d0), "=r"(d1), "=r"(d2), "=r"(d3) : "r"(addr))

__device__ __forceinline__ void split2pack(float x, float y,
                                           uint32_t& hi, uint32_t& lo)
{
    __nv_bfloat16 hx = __float2bfloat16(x), hy = __float2bfloat16(y);
    __nv_bfloat16 lx = __float2bfloat16(x - __bfloat162float(hx));
    __nv_bfloat16 ly = __float2bfloat16(y - __bfloat162float(hy));
    __nv_bfloat162 th = __halves2bfloat162(hx, hy);
    __nv_bfloat162 tl = __halves2bfloat162(lx, ly);
    hi = *reinterpret_cast<uint32_t*>(&th);
    lo = *reinterpret_cast<uint32_t*>(&tl);
}

// ---------------- rope table (fp64 once, tiny) -----------------------------
__global__ void rope_table_kernel()
{
    int idx = blockIdx.x * blockDim.x + threadIdx.x;
    if (idx >= S_LEN * 64) return;
    int pos = idx >> 6;
    int i   = idx & 63;
    double inv = exp(-((double)(2 * i) / 128.0) * 9.210340371976184);
    double f   = (double)pos * inv;
    g_cs[idx] = make_float2((float)cos(f), (float)sin(f));
}

// ---------------- split fp32 -> bf16 hi/lo ---------------------------------
__global__ void split_kernel(const float* __restrict__ x,
                             __nv_bfloat16* __restrict__ hi,
                             __nv_bfloat16* __restrict__ lo, int n2)
{
    int i = blockIdx.x * blockDim.x + threadIdx.x;
    if (i >= n2) return;
    float2 v = ((const float2*)x)[i];
    __nv_bfloat16 h0 = __float2bfloat16(v.x);
    __nv_bfloat16 h1 = __float2bfloat16(v.y);
    __nv_bfloat16 l0 = __float2bfloat16(v.x - __bfloat162float(h0));
    __nv_bfloat16 l1 = __float2bfloat16(v.y - __bfloat162float(h1));
    ((__nv_bfloat162*)hi)[i] = __halves2bfloat162(h0, h1);
    ((__nv_bfloat162*)lo)[i] = __halves2bfloat162(l0, l1);
}

// ---------------- rope + split: fp32 in -> bf16 hi/lo out ------------------
__global__ void rope_split_kernel(const float* __restrict__ X,
                                  __nv_bfloat16* __restrict__ Xh,
                                  __nv_bfloat16* __restrict__ Xl, float scale)
{
    int idx = blockIdx.x * blockDim.x + threadIdx.x;
    if (idx >= TOKENS * NH * 64) return;
    int i  = idx & 63;
    int hh = (idx >> 6) & (NH - 1);
    int t  = idx >> 10;
    int pos = t & (S_LEN - 1);

    float2 cs = g_cs[pos * 64 + i];
    const float* p = X + (size_t)t * D_MODEL + hh * DH;
    float x1 = p[i];
    float x2 = p[i + 64];
    float y1 = (x1 * cs.x - x2 * cs.y) * scale;
    float y2 = (x2 * cs.x + x1 * cs.y) * scale;

    size_t o = (size_t)t * D_MODEL + hh * DH;
    __nv_bfloat16 h1 = __float2bfloat16(y1);
    __nv_bfloat16 h2 = __float2bfloat16(y2);
    Xh[o + i]      = h1;
    Xl[o + i]      = __float2bfloat16(y1 - __bfloat162float(h1));
    Xh[o + i + 64] = h2;
    Xl[o + i + 64] = __float2bfloat16(y2 - __bfloat162float(h2));
}

// ---------------- transpose + split: W[K][N] -> BT[N][K] bf16 hi/lo --------
__global__ void tsplit_kernel(const float* __restrict__ W,
                              __nv_bfloat16* __restrict__ hiT,
                              __nv_bfloat16* __restrict__ loT)
{
    __shared__ float tile[32][33];
    int tx = threadIdx.x, ty = threadIdx.y;
    int x0 = blockIdx.x * 32, y0 = blockIdx.y * 32;
    #pragma unroll
    for (int j = 0; j < 32; j += 8)
        tile[ty + j][tx] = W[(size_t)(y0 + ty + j) * D_MODEL + x0 + tx];
    __syncthreads();
    #pragma unroll
    for (int j = 0; j < 32; j += 8) {
        float v = tile[tx][ty + j];
        __nv_bfloat16 h = __float2bfloat16(v);
        __nv_bfloat16 l = __float2bfloat16(v - __bfloat162float(h));
        size_t o = (size_t)(x0 + ty + j) * D_MODEL + y0 + tx;
        hiT[o] = h;
        loT[o] = l;
    }
}

// ---------------- bf16x3 tensor-core GEMM (ldmatrix) -----------------------
#define TBM 128
#define TBN 128
#define TBK 32
#define TS  40    // halves; 80B row stride -> conflict-free LDSM

__global__ void __launch_bounds__(256, 2) gemm_bf16x3_kernel(
    const __nv_bfloat16* __restrict__ Ah, const __nv_bfloat16* __restrict__ Al,
    const __nv_bfloat16* __restrict__ BTh, const __nv_bfloat16* __restrict__ BTl,
    float* __restrict__ C)
{
    const int K = D_MODEL, N = D_MODEL;
    __shared__ __align__(16) __nv_bfloat16 sAh[TBM * TS];
    __shared__ __align__(16) __nv_bfloat16 sAl[TBM * TS];
    __shared__ __align__(16) __nv_bfloat16 sBh[TBN * TS];
    __shared__ __align__(16) __nv_bfloat16 sBl[TBN * TS];

    const int t = threadIdx.x;
    const int bm = blockIdx.y, bn = blockIdx.x;
    const int warp = t >> 5, lane = t & 31;
    const int wm = warp >> 2;
    const int wn = warp & 3;
    const int g  = lane >> 2;
    const int tq = lane & 3;

    const uint32_t cAh = (uint32_t)__cvta_generic_to_shared(sAh);
    const uint32_t cAl = (uint32_t)__cvta_generic_to_shared(sAl);
    const uint32_t cBh = (uint32_t)__cvta_generic_to_shared(sBh);
    const uint32_t cBl = (uint32_t)__cvta_generic_to_shared(sBl);
    // per-lane ldmatrix offsets (bytes)
    const uint32_t aoff = (uint32_t)(((wm * 64 + (lane & 15)) * TS + ((lane >> 4) * 8)) * 2);
    const uint32_t boff = (uint32_t)(((wn * 32 + (lane & 7) + ((lane >> 4) * 8)) * TS
                                     + (((lane >> 3) & 1) * 8)) * 2);

    float acc[4][4][4];
    #pragma unroll
    for (int a = 0; a < 4; a++)
        #pragma unroll
        for (int b = 0; b < 4; b++)
            #pragma unroll
            for (int c = 0; c < 4; c++) acc[a][b][c] = 0.0f;

    for (int k0 = 0; k0 < K; k0 += TBK) {
        __syncthreads();
        #pragma unroll
        for (int rep = 0; rep < 2; rep++) {
            int idx = t + rep * 256;
            int r = idx >> 2;
            int c = (idx & 3) * 8;
            size_t ga = (size_t)(bm * TBM + r) * K + k0 + c;
            size_t gb = (size_t)(bn * TBN + r) * K + k0 + c;
            *(uint4*)&sAh[r * TS + c] = *(const uint4*)(Ah + ga);
            *(uint4*)&sAl[r * TS + c] = *(const uint4*)(Al + ga);
            *(uint4*)&sBh[r * TS + c] = *(const uint4*)(BTh + gb);
            *(uint4*)&sBl[r * TS + c] = *(const uint4*)(BTl + gb);
        }
        __syncthreads();

        #pragma unroll
        for (int ks = 0; ks < 2; ks++) {          // two 16-wide k-steps
            const uint32_t kofs = ks * 32;        // 16 halves
            uint32_t fah[4][4], fal[4][4], fbh[4][2], fbl[4][2];
            #pragma unroll
            for (int mf = 0; mf < 4; mf++) {
                uint32_t ad = aoff + mf * (16 * TS * 2) + kofs;
                LDSM_X4(fah[mf][0], fah[mf][1], fah[mf][2], fah[mf][3], cAh + ad);
                LDSM_X4(fal[mf][0], fal[mf][1], fal[mf][2], fal[mf][3], cAl + ad);
            }
            #pragma unroll
            for (int p = 0; p < 2; p++) {
                uint32_t bd = boff + p * (16 * TS * 2) + kofs;
                LDSM_X4(fbh[2*p][0], fbh[2*p][1], fbh[2*p+1][0], fbh[2*p+1][1], cBh + bd);
                LDSM_X4(fbl[2*p][0], fbl[2*p][1], fbl[2*p+1][0], fbl[2*p+1][1], cBl + bd);
            }
            #pragma unroll
            for (int mf = 0; mf < 4; mf++)
                #pragma unroll
                for (int nf = 0; nf < 4; nf++) {
                    MMA16816(acc[mf][nf], fah[mf], fbh[nf]);
                    MMA16816(acc[mf][nf], fah[mf], fbl[nf]);
                    MMA16816(acc[mf][nf], fal[mf], fbh[nf]);
                }
        }
    }

    #pragma unroll
    for (int mf = 0; mf < 4; mf++) {
        int row = bm * TBM + wm * 64 + mf * 16 + g;
        #pragma unroll
        for (int nf = 0; nf < 4; nf++) {
            int col = bn * TBN + wn * 32 + nf * 8 + tq * 2;
            *(float2*)&C[(size_t)row * N + col] =
                make_float2(acc[mf][nf][0], acc[mf][nf][1]);
            *(float2*)&C[(size_t)(row + 8) * N + col] =
                make_float2(acc[mf][nf][2], acc[mf][nf][3]);
        }
    }
}

// ---------------- tensor-core flash attention (bf16x3, causal) -------------
#define AT_SQ 136          // Q/K smem stride (halves): 272B = 17*16, conflict-free
#define AT_SV 72           // V^T smem stride (halves): 144B = 9*16
#define AT_KV 9216         // union buffer size (halves) = max(64*136, 128*72)
#define ATT_SMEM ((2 * 64 * AT_SQ + 2 * AT_KV) * 2)

__global__ void __launch_bounds__(128) attn_tc_kernel(
    const __nv_bfloat16* __restrict__ Qh, const __nv_bfloat16* __restrict__ Ql,
    const __nv_bfloat16* __restrict__ Kh, const __nv_bfloat16* __restrict__ Kl,
    const __nv_bfloat16* __restrict__ Vh, const __nv_bfloat16* __restrict__ Vl,
    float* __restrict__ O)
{
    const int b = blockIdx.z, h = blockIdx.y, qb = blockIdx.x;
    const int tid = threadIdx.x, warp = tid >> 5, lane = tid & 31;
    const int g = lane >> 2, tq = lane & 3;

    extern __shared__ __nv_bfloat16 sh[];
    __nv_bfloat16* sQh  = sh;
    __nv_bfloat16* sQl  = sQh + 64 * AT_SQ;
    __nv_bfloat16* sKVh = sQl + 64 * AT_SQ;
    __nv_bfloat16* sKVl = sKVh + AT_KV;

    const size_t base = ((size_t)b * S_LEN) * D_MODEL + (size_t)h * DH;

    // stage Q tile (64 rows x 128 dh), straight copy
    for (int i = tid; i < 64 * 16; i += 128) {
        int r = i >> 4, c = (i & 15) << 3;
        size_t src = base + (size_t)(qb * 64 + r) * D_MODEL + c;
        *(uint4*)&sQh[r * AT_SQ + c] = *(const uint4*)(Qh + src);
        *(uint4*)&sQl[r * AT_SQ + c] = *(const uint4*)(Ql + src);
    }

    float o[16][4];
    #pragma unroll
    for (int nf = 0; nf < 16; nf++)
        #pragma unroll
        for (int c = 0; c < 4; c++) o[nf][c] = 0.0f;
    float mr0 = -INFINITY, mr1 = -INFINITY, lr0 = 0.0f, lr1 = 0.0f;

    const uint32_t cQh  = (uint32_t)__cvta_generic_to_shared(sQh);
    const uint32_t cQl  = (uint32_t)__cvta_generic_to_shared(sQl);
    const uint32_t cKVh = (uint32_t)__cvta_generic_to_shared(sKVh);
    const uint32_t cKVl = (uint32_t)__cvta_generic_to_shared(sKVl);
    const uint32_t aoff  = (uint32_t)(((warp * 16 + (lane & 15)) * AT_SQ + ((lane >> 4) * 8)) * 2);
    const uint32_t boffK = (uint32_t)((((lane & 7) + ((lane >> 4) * 8)) * AT_SQ
                                      + (((lane >> 3) & 1) * 8)) * 2);
    const uint32_t boffV = (uint32_t)((((lane & 7) + ((lane >> 4) * 8)) * AT_SV
                                      + (((lane >> 3) & 1) * 8)) * 2);

    for (int kb = 0; kb <= qb; kb++) {
        __syncthreads();   // prior PV done reading V; also covers Q-store on iter 0
        for (int i = tid; i < 64 * 16; i += 128) {
            int r = i >> 4, c = (i & 15) << 3;
            size_t src = base + (size_t)(kb * 64 + r) * D_MODEL + c;
            *(uint4*)&sKVh[r * AT_SQ + c] = *(const uint4*)(Kh + src);
            *(uint4*)&sKVl[r * AT_SQ + c] = *(const uint4*)(Kl + src);
        }
        __syncthreads();

        // ---- S = Q K^T (16 x 64 per warp), bf16x3 ----
        float s[8][4];
        #pragma unroll
        for (int tt = 0; tt < 8; tt++)
            #pragma unroll
            for (int c = 0; c < 4; c++) s[tt][c] = 0.0f;

        #pragma unroll
        for (int ks = 0; ks < 8; ks++) {
            uint32_t qh[4], ql[4];
            LDSM_X4(qh[0], qh[1], qh[2], qh[3], cQh + aoff + ks * 32);
            LDSM_X4(ql[0], ql[1], ql[2], ql[3], cQl + aoff + ks * 32);
            #pragma unroll
            for (int p = 0; p < 4; p++) {
                uint32_t kh[4], kl[4];
                uint32_t bd = boffK + p * (16 * AT_SQ * 2) + ks * 32;
                LDSM_X4(kh[0], kh[1], kh[2], kh[3], cKVh + bd);
                LDSM_X4(kl[0], kl[1], kl[2], kl[3], cKVl + bd);
                uint32_t bh0[2] = {kh[0], kh[1]}, bh1[2] = {kh[2], kh[3]};
                uint32_t bl0[2] = {kl[0], kl[1]}, bl1[2] = {kl[2], kl[3]};
                MMA16816(s[2*p],     qh, bh0);
                MMA16816(s[2*p],     ql, bh0);
                MMA16816(s[2*p],     qh, bl0);
                MMA16816(s[2*p + 1], qh, bh1);
                MMA16816(s[2*p + 1], ql, bh1);
                MMA16816(s[2*p + 1], qh, bl1);
            }
        }

        if (kb == qb) {
            int r0 = warp * 16 + g, r1 = r0 + 8;
            #pragma unroll
            for (int tt = 0; tt < 8; tt++) {
                int c0 = tt * 8 + tq * 2;
                if (c0     > r0) s[tt][0] = -INFINITY;
                if (c0 + 1 > r0) s[tt][1] = -INFINITY;
                if (c0     > r1) s[tt][2] = -INFINITY;
                if (c0 + 1 > r1) s[tt][3] = -INFINITY;
            }
        }

        // ---- online softmax (rows g, g+8) ----
        float mx0 = -INFINITY, mx1 = -INFINITY;
        #pragma unroll
        for (int tt = 0; tt < 8; tt++) {
            mx0 = fmaxf(mx0, fmaxf(s[tt][0], s[tt][1]));
            mx1 = fmaxf(mx1, fmaxf(s[tt][2], s[tt][3]));
        }
        mx0 = fmaxf(mx0, __shfl_xor_sync(0xffffffffu, mx0, 1));
        mx0 = fmaxf(mx0, __shfl_xor_sync(0xffffffffu, mx0, 2));
        mx1 = fmaxf(mx1, __shfl_xor_sync(0xffffffffu, mx1, 1));
        mx1 = fmaxf(mx1, __shfl_xor_sync(0xffffffffu, mx1, 2));

        float mn0 = fmaxf(mr0, mx0), mn1 = fmaxf(mr1, mx1);
        float al0 = __expf(mr0 - mn0), al1 = __expf(mr1 - mn1);
        float sum0 = 0.0f, sum1 = 0.0f;
        #pragma unroll
        for (int tt = 0; tt < 8; tt++) {
            s[tt][0] = __expf(s[tt][0] - mn0);
            s[tt][1] = __expf(s[tt][1] - mn0);
            s[tt][2] = __expf(s[tt][2] - mn1);
            s[tt][3] = __expf(s[tt][3] - mn1);
            sum0 += s[tt][0] + s[tt][1];
            sum1 += s[tt][2] + s[tt][3];
        }
        sum0 += __shfl_xor_sync(0xffffffffu, sum0, 1);
        sum0 += __shfl_xor_sync(0xffffffffu, sum0, 2);
        sum1 += __shfl_xor_sync(0xffffffffu, sum1, 1);
        sum1 += __shfl_xor_sync(0xffffffffu, sum1, 2);
        lr0 = lr0 * al0 + sum0;
        lr1 = lr1 * al1 + sum1;
        mr0 = mn0;
        mr1 = mn1;
        #pragma unroll
        for (int nf = 0; nf < 16; nf++) {
            o[nf][0] *= al0; o[nf][1] *= al0;
            o[nf][2] *= al1; o[nf][3] *= al1;
        }

        __syncthreads();   // all warps done reading K
        // ---- stage V^T (128 d-rows x 64 kv) bf16 hi/lo ----
        {
            int kv = tid & 63, dh2 = tid >> 6;
            size_t srow = base + (size_t)(kb * 64 + kv) * D_MODEL + dh2 * 64;
            #pragma unroll
            for (int i2 = 0; i2 < 32; i2++) {
                int d = dh2 * 64 + i2 * 2;
                __nv_bfloat162 vh2 = *(const __nv_bfloat162*)(Vh + srow + i2 * 2);
                __nv_bfloat162 vl2 = *(const __nv_bfloat162*)(Vl + srow + i2 * 2);
                sKVh[d * AT_SV + kv]       = vh2.x;
                sKVh[(d + 1) * AT_SV + kv] = vh2.y;
                sKVl[d * AT_SV + kv]       = vl2.x;
                sKVl[(d + 1) * AT_SV + kv] = vl2.y;
            }
        }
        __syncthreads();

        // ---- O += P V  (P from registers, split hi/lo) ----
        #pragma unroll
        for (int j = 0; j < 4; j++) {
            uint32_t ph[4], pl[4];
            split2pack(s[2*j][0],     s[2*j][1],     ph[0], pl[0]);
            split2pack(s[2*j][2],     s[2*j][3],     ph[1], pl[1]);
            split2pack(s[2*j + 1][0], s[2*j + 1][1], ph[2], pl[2]);
            split2pack(s[2*j + 1][2], s[2*j + 1][3], ph[3], pl[3]);
            #pragma unroll
            for (int p = 0; p < 8; p++) {
                uint32_t vh4[4], vl4[4];
                uint32_t bd = boffV + p * (16 * AT_SV * 2) + j * 32;
                LDSM_X4(vh4[0], vh4[1], vh4[2], vh4[3], cKVh + bd);
                LDSM_X4(vl4[0], vl4[1], vl4[2], vl4[3], cKVl + bd);
                uint32_t bh0[2] = {vh4[0], vh4[1]}, bh1[2] = {vh4[2], vh4[3]};
                uint32_t bl0[2] = {vl4[0], vl4[1]}, bl1[2] = {vl4[2], vl4[3]};
                MMA16816(o[2*p],     ph, bh0);
                MMA16816(o[2*p],     pl, bh0);
                MMA16816(o[2*p],     ph, bl0);
                MMA16816(o[2*p + 1], ph, bh1);
                MMA16816(o[2*p + 1], pl, bh1);
                MMA16816(o[2*p + 1], ph, bl1);
            }
        }
    }

    // epilogue
    float inv0 = 1.0f / lr0, inv1 = 1.0f / lr1;
    int r0 = qb * 64 + warp * 16 + g;
    #pragma unroll
    for (int nf = 0; nf < 16; nf++) {
        int c = nf * 8 + tq * 2;
        *(float2*)&O[base + (size_t)r0 * D_MODEL + c] =
            make_float2(o[nf][0] * inv0, o[nf][1] * inv0);
        *(float2*)&O[base + (size_t)(r0 + 8) * D_MODEL + c] =
            make_float2(o[nf][2] * inv1, o[nf][3] * inv1);
    }
}

// ---------------- launch ----------------------------------------------------
extern "C" void kernel_launch(void* const* d_in, const int* in_sizes, int n_in,
                              void* d_out, int out_size)
{
    (void)in_sizes; (void)n_in; (void)out_size;
    const float* hidden = (const float*)d_in[0];
    const float* Wq = (const float*)d_in[3];
    const float* Wk = (const float*)d_in[4];
    const float* Wv = (const float*)d_in[5];
    const float* Wo = (const float*)d_in[6];
    float* out = (float*)d_out;

    float *Qp, *Kp, *Vp, *Op;
    __nv_bfloat16 *Ahp, *Alp, *Bhp, *Blp;
    __nv_bfloat16 *Qhp, *Qlp, *Khp, *Klp, *Vhp, *Vlp;
    cudaGetSymbolAddress((void**)&Qp, g_Q);
    cudaGetSymbolAddress((void**)&Kp, g_K);
    cudaGetSymbolAddress((void**)&Vp, g_V);
    cudaGetSymbolAddress((void**)&Op, g_O);
    cudaGetSymbolAddress((void**)&Ahp, g_Ah);
    cudaGetSymbolAddress((void**)&Alp, g_Al);
    cudaGetSymbolAddress((void**)&Bhp, g_Bh);
    cudaGetSymbolAddress((void**)&Blp, g_Bl);
    cudaGetSymbolAddress((void**)&Qhp, g_Qh);
    cudaGetSymbolAddress((void**)&Qlp, g_Ql);
    cudaGetSymbolAddress((void**)&Khp, g_Kh);
    cudaGetSymbolAddress((void**)&Klp, g_Kl);
    cudaGetSymbolAddress((void**)&Vhp, g_Vh);
    cudaGetSymbolAddress((void**)&Vlp, g_Vl);

    rope_table_kernel<<<(S_LEN * 64 + 255) / 256, 256>>>();

    int n2 = TOKENS * D_MODEL / 2;
    split_kernel<<<(n2 + 255) / 256, 256>>>(hidden, Ahp, Alp, n2);

    dim3 tgrid(D_MODEL / 32, D_MODEL / 32);
    dim3 tblk(32, 8);
    dim3 ggrid(D_MODEL / TBN, TOKENS / TBM);

    tsplit_kernel<<<tgrid, tblk>>>(Wq, Bhp, Blp);
    gemm_bf16x3_kernel<<<ggrid, 256>>>(Ahp, Alp, Bhp, Blp, Qp);
    tsplit_kernel<<<tgrid, tblk>>>(Wk, Bhp, Blp);
    gemm_bf16x3_kernel<<<ggrid, 256>>>(Ahp, Alp, Bhp, Blp, Kp);
    tsplit_kernel<<<tgrid, tblk>>>(Wv, Bhp, Blp);
    gemm_bf16x3_kernel<<<ggrid, 256>>>(Ahp, Alp, Bhp, Blp, Vp);

    int nrope = TOKENS * NH * 64;
    rope_split_kernel<<<(nrope + 255) / 256, 256>>>(Qp, Qhp, Qlp, 0.08838834764831845f);
    rope_split_kernel<<<(nrope + 255) / 256, 256>>>(Kp, Khp, Klp, 1.0f);
    split_kernel<<<(n2 + 255) / 256, 256>>>(Vp, Vhp, Vlp, n2);

    cudaFuncSetAttribute(attn_tc_kernel, cudaFuncAttributeMaxDynamicSharedMemorySize, ATT_SMEM);
    attn_tc_kernel<<<dim3(S_LEN / 64, NH, BATCH), 128, ATT_SMEM>>>(
        Qhp, Qlp, Khp, Klp, Vhp, Vlp, Op);

    split_kernel<<<(n2 + 255) / 256, 256>>>(Op, Ahp, Alp, n2);
    tsplit_kernel<<<tgrid, tblk>>>(Wo, Bhp, Blp);
    gemm_bf16x3_kernel<<<ggrid, 256>>>(Ahp, Alp, Bhp, Blp, out);
}

// round 11
// speedup vs baseline: 3.2077x; 1.3575x over previous
#include <cuda_runtime.h>
#include <cuda_bf16.h>
#include <cstdint>
#include <math.h>

#define S_LEN   2048
#define D_MODEL 2048
#define NH      16
#define DH      128
#define BATCH   2
#define TOKENS  (BATCH * S_LEN)   // 4096

// ---------------- scratch (device globals: allocation-free) ----------------
__device__ float g_Q[TOKENS * D_MODEL];
__device__ float g_K[TOKENS * D_MODEL];
__device__ float g_V[TOKENS * D_MODEL];
__device__ float g_O[TOKENS * D_MODEL];
__device__ __nv_bfloat16 g_Ah[TOKENS * D_MODEL];
__device__ __nv_bfloat16 g_Al[TOKENS * D_MODEL];
__device__ __nv_bfloat16 g_Bh[D_MODEL * D_MODEL];
__device__ __nv_bfloat16 g_Bl[D_MODEL * D_MODEL];
__device__ __nv_bfloat16 g_Qh[TOKENS * D_MODEL];
__device__ __nv_bfloat16 g_Ql[TOKENS * D_MODEL];
__device__ __nv_bfloat16 g_Kh[TOKENS * D_MODEL];
__device__ __nv_bfloat16 g_Kl[TOKENS * D_MODEL];
__device__ __nv_bfloat16 g_Vh[TOKENS * D_MODEL];
__device__ __nv_bfloat16 g_Vl[TOKENS * D_MODEL];
__device__ float2 g_cs[S_LEN * 64];

// ---------------- common asm helpers ---------------------------------------
#define MMA16816(d, a, b)                                                     \
    asm volatile(                                                             \
        "mma.sync.aligned.m16n8k16.row.col.f32.bf16.bf16.f32 "                \
        "{%0,%1,%2,%3},{%4,%5,%6,%7},{%8,%9},{%0,%1,%2,%3};\n"                \
        : "+f"(d[0]), "+f"(d[1]), "+f"(d[2]), "+f"(d[3])                      \
        : "r"(a[0]), "r"(a[1]), "r"(a[2]), "r"(a[3]), "r"(b[0]), "r"(b[1]))

#define LDSM_X4(d0, d1, d2, d3, addr)                                         \
    asm volatile("ldmatrix.sync.aligned.m8n8.x4.shared.b16 {%0,%1,%2,%3}, [%4];" \
                 : "=r"(d0), "=r"(d1), "=r"(d2), "=r"(d3) : "r"(addr))

#define LDSM_X4_T(d0, d1, d2, d3, addr)                                       \
    asm volatile("ldmatrix.sync.aligned.m8n8.x4.trans.shared.b16 {%0,%1,%2,%3}, [%4];" \
                 : "=r"(d0), "=r"(d1), "=r"(d2), "=r"(d3) : "r"(addr))

#define CP16(dst, src)                                                        \
    asm volatile("cp.async.cg.shared.global [%0], [%1], 16;\n"                \
                 :: "r"(dst), "l"(src))
#define CP_COMMIT() asm volatile("cp.async.commit_group;\n" ::: "memory")
#define CP_WAIT1()  asm volatile("cp.async.wait_group 1;\n" ::: "memory")
#define CP_WAIT0()  asm volatile("cp.async.wait_group 0;\n" ::: "memory")

__device__ __forceinline__ void split2pack(float x, float y,
                                           uint32_t& hi, uint32_t& lo)
{
    __nv_bfloat16 hx = __float2bfloat16(x), hy = __float2bfloat16(y);
    __nv_bfloat16 lx = __float2bfloat16(x - __bfloat162float(hx));
    __nv_bfloat16 ly = __float2bfloat16(y - __bfloat162float(hy));
    __nv_bfloat162 th = __halves2bfloat162(hx, hy);
    __nv_bfloat162 tl = __halves2bfloat162(lx, ly);
    hi = *reinterpret_cast<uint32_t*>(&th);
    lo = *reinterpret_cast<uint32_t*>(&tl);
}

// ---------------- rope table (fp64 once, tiny) -----------------------------
__global__ void rope_table_kernel()
{
    int idx = blockIdx.x * blockDim.x + threadIdx.x;
    if (idx >= S_LEN * 64) return;
    int pos = idx >> 6;
    int i   = idx & 63;
    double inv = exp(-((double)(2 * i) / 128.0) * 9.210340371976184);
    double f   = (double)pos * inv;
    g_cs[idx] = make_float2((float)cos(f), (float)sin(f));
}

// ---------------- split fp32 -> bf16 hi/lo ---------------------------------
__global__ void split_kernel(const float* __restrict__ x,
                             __nv_bfloat16* __restrict__ hi,
                             __nv_bfloat16* __restrict__ lo, int n2)
{
    int i = blockIdx.x * blockDim.x + threadIdx.x;
    if (i >= n2) return;
    float2 v = ((const float2*)x)[i];
    __nv_bfloat16 h0 = __float2bfloat16(v.x);
    __nv_bfloat16 h1 = __float2bfloat16(v.y);
    __nv_bfloat16 l0 = __float2bfloat16(v.x - __bfloat162float(h0));
    __nv_bfloat16 l1 = __float2bfloat16(v.y - __bfloat162float(h1));
    ((__nv_bfloat162*)hi)[i] = __halves2bfloat162(h0, h1);
    ((__nv_bfloat162*)lo)[i] = __halves2bfloat162(l0, l1);
}

// ---------------- rope + split: fp32 in -> bf16 hi/lo out ------------------
__global__ void rope_split_kernel(const float* __restrict__ X,
                                  __nv_bfloat16* __restrict__ Xh,
                                  __nv_bfloat16* __restrict__ Xl, float scale)
{
    int idx = blockIdx.x * blockDim.x + threadIdx.x;
    if (idx >= TOKENS * NH * 64) return;
    int i  = idx & 63;
    int hh = (idx >> 6) & (NH - 1);
    int t  = idx >> 10;
    int pos = t & (S_LEN - 1);

    float2 cs = g_cs[pos * 64 + i];
    const float* p = X + (size_t)t * D_MODEL + hh * DH;
    float x1 = p[i];
    float x2 = p[i + 64];
    float y1 = (x1 * cs.x - x2 * cs.y) * scale;
    float y2 = (x2 * cs.x + x1 * cs.y) * scale;

    size_t o = (size_t)t * D_MODEL + hh * DH;
    __nv_bfloat16 h1 = __float2bfloat16(y1);
    __nv_bfloat16 h2 = __float2bfloat16(y2);
    Xh[o + i]      = h1;
    Xl[o + i]      = __float2bfloat16(y1 - __bfloat162float(h1));
    Xh[o + i + 64] = h2;
    Xl[o + i + 64] = __float2bfloat16(y2 - __bfloat162float(h2));
}

// ---------------- transpose + split: W[K][N] -> BT[N][K] bf16 hi/lo --------
__global__ void tsplit_kernel(const float* __restrict__ W,
                              __nv_bfloat16* __restrict__ hiT,
                              __nv_bfloat16* __restrict__ loT)
{
    __shared__ float tile[32][33];
    int tx = threadIdx.x, ty = threadIdx.y;
    int x0 = blockIdx.x * 32, y0 = blockIdx.y * 32;
    #pragma unroll
    for (int j = 0; j < 32; j += 8)
        tile[ty + j][tx] = W[(size_t)(y0 + ty + j) * D_MODEL + x0 + tx];
    __syncthreads();
    #pragma unroll
    for (int j = 0; j < 32; j += 8) {
        float v = tile[tx][ty + j];
        __nv_bfloat16 h = __float2bfloat16(v);
        __nv_bfloat16 l = __float2bfloat16(v - __bfloat162float(h));
        size_t o = (size_t)(x0 + ty + j) * D_MODEL + y0 + tx;
        hiT[o] = h;
        loT[o] = l;
    }
}

// ---------------- bf16x3 GEMM: cp.async 2-stage pipeline -------------------
#define TBM 128
#define TBN 128
#define TBK 32
#define TS  40                     // halves per row (padded)
#define TSZ (TBM * TS)             // halves per array
#define ASZ (TSZ * 2)              // bytes per array
#define STAGE_B (4 * ASZ)          // bytes per stage
#define GEMM_SMEM (2 * STAGE_B)    // 81920 B

__global__ void __launch_bounds__(256, 2) gemm_bf16x3_kernel(
    const __nv_bfloat16* __restrict__ Ah, const __nv_bfloat16* __restrict__ Al,
    const __nv_bfloat16* __restrict__ BTh, const __nv_bfloat16* __restrict__ BTl,
    float* __restrict__ C)
{
    const int K = D_MODEL, N = D_MODEL;
    extern __shared__ __nv_bfloat16 gsm[];
    const uint32_t cBase = (uint32_t)__cvta_generic_to_shared(gsm);

    const int t = threadIdx.x;
    const int bm = blockIdx.y, bn = blockIdx.x;
    const int warp = t >> 5, lane = t & 31;
    const int wm = warp >> 2;
    const int wn = warp & 3;
    const int g  = lane >> 2;
    const int tq = lane & 3;

    const uint32_t aoff = (uint32_t)(((wm * 64 + (lane & 15)) * TS + ((lane >> 4) * 8)) * 2);
    const uint32_t boff = (uint32_t)(((wn * 32 + (lane & 7) + ((lane >> 4) * 8)) * TS
                                     + (((lane >> 3) & 1) * 8)) * 2);
    const int lr = t >> 2;
    const int lc = (t & 3) * 8;

    float acc[4][4][4];
    #pragma unroll
    for (int a = 0; a < 4; a++)
        #pragma unroll
        for (int b = 0; b < 4; b++)
            #pragma unroll
            for (int c = 0; c < 4; c++) acc[a][b][c] = 0.0f;

    const int KT = K / TBK;   // 64

    // prologue: stage 0
    {
        #pragma unroll
        for (int rep = 0; rep < 2; rep++) {
            int r = lr + rep * 64;
            size_t ga = (size_t)(bm * TBM + r) * K + lc;
            size_t gb = (size_t)(bn * TBN + r) * K + lc;
            uint32_t ds = cBase + (uint32_t)((r * TS + lc) * 2);
            CP16(ds,            Ah + ga);
            CP16(ds + ASZ,      Al + ga);
            CP16(ds + 2 * ASZ,  BTh + gb);
            CP16(ds + 3 * ASZ,  BTl + gb);
        }
        CP_COMMIT();
    }

    for (int kt = 0; kt < KT; kt++) {
        if (kt + 1 < KT) {
            int k0 = (kt + 1) * TBK;
            uint32_t sb = cBase + ((kt + 1) & 1) * STAGE_B;
            #pragma unroll
            for (int rep = 0; rep < 2; rep++) {
                int r = lr + rep * 64;
                size_t ga = (size_t)(bm * TBM + r) * K + k0 + lc;
                size_t gb = (size_t)(bn * TBN + r) * K + k0 + lc;
                uint32_t ds = sb + (uint32_t)((r * TS + lc) * 2);
                CP16(ds,            Ah + ga);
                CP16(ds + ASZ,      Al + ga);
                CP16(ds + 2 * ASZ,  BTh + gb);
                CP16(ds + 3 * ASZ,  BTl + gb);
            }
            CP_COMMIT();
            CP_WAIT1();
        } else {
            CP_WAIT0();
        }
        __syncthreads();

        const uint32_t sb = cBase + (kt & 1) * STAGE_B;
        #pragma unroll
        for (int ks = 0; ks < 2; ks++) {
            const uint32_t kofs = ks * 32;
            uint32_t fah[4][4], fal[4][4], fbh[4][2], fbl[4][2];
            #pragma unroll
            for (int mf = 0; mf < 4; mf++) {
                uint32_t ad = sb + aoff + mf * (16 * TS * 2) + kofs;
                LDSM_X4(fah[mf][0], fah[mf][1], fah[mf][2], fah[mf][3], ad);
                LDSM_X4(fal[mf][0], fal[mf][1], fal[mf][2], fal[mf][3], ad + ASZ);
            }
            #pragma unroll
            for (int p = 0; p < 2; p++) {
                uint32_t bd = sb + 2 * ASZ + boff + p * (16 * TS * 2) + kofs;
                LDSM_X4(fbh[2*p][0], fbh[2*p][1], fbh[2*p+1][0], fbh[2*p+1][1], bd);
                LDSM_X4(fbl[2*p][0], fbl[2*p][1], fbl[2*p+1][0], fbl[2*p+1][1], bd + ASZ);
            }
            #pragma unroll
            for (int mf = 0; mf < 4; mf++)
                #pragma unroll
                for (int nf = 0; nf < 4; nf++) {
                    MMA16816(acc[mf][nf], fah[mf], fbh[nf]);
                    MMA16816(acc[mf][nf], fah[mf], fbl[nf]);
                    MMA16816(acc[mf][nf], fal[mf], fbh[nf]);
                }
        }
        __syncthreads();
    }

    #pragma unroll
    for (int mf = 0; mf < 4; mf++) {
        int row = bm * TBM + wm * 64 + mf * 16 + g;
        #pragma unroll
        for (int nf = 0; nf < 4; nf++) {
            int col = bn * TBN + wn * 32 + nf * 8 + tq * 2;
            *(float2*)&C[(size_t)row * N + col] =
                make_float2(acc[mf][nf][0], acc[mf][nf][1]);
            *(float2*)&C[(size_t)(row + 8) * N + col] =
                make_float2(acc[mf][nf][2], acc[mf][nf][3]);
        }
    }
}

// ---------------- tensor-core flash attention (bf16x3, causal) -------------
#define AT_SD 136          // smem stride (halves): 272B, LDSM conflict-free
#define AT_TILE (64 * AT_SD)
#define ATT_SMEM (6 * AT_TILE * 2)   // Qh,Ql,Kh,Kl,Vh,Vl  = 104448 B

__global__ void __launch_bounds__(128) attn_tc_kernel(
    const __nv_bfloat16* __restrict__ Qh, const __nv_bfloat16* __restrict__ Ql,
    const __nv_bfloat16* __restrict__ Kh, const __nv_bfloat16* __restrict__ Kl,
    const __nv_bfloat16* __restrict__ Vh, const __nv_bfloat16* __restrict__ Vl,
    float* __restrict__ O)
{
    const int b = blockIdx.z, h = blockIdx.y, qb = blockIdx.x;
    const int tid = threadIdx.x, warp = tid >> 5, lane = tid & 31;
    const int g = lane >> 2, tq = lane & 3;

    extern __shared__ __nv_bfloat16 sh[];
    __nv_bfloat16* sQh = sh;
    __nv_bfloat16* sQl = sQh + AT_TILE;
    __nv_bfloat16* sKh = sQl + AT_TILE;
    __nv_bfloat16* sKl = sKh + AT_TILE;
    __nv_bfloat16* sVh = sKl + AT_TILE;
    __nv_bfloat16* sVl = sVh + AT_TILE;

    const size_t base = ((size_t)b * S_LEN) * D_MODEL + (size_t)h * DH;

    // stage Q tile (64 rows x 128 dh)
    for (int i = tid; i < 64 * 16; i += 128) {
        int r = i >> 4, c = (i & 15) << 3;
        size_t src = base + (size_t)(qb * 64 + r) * D_MODEL + c;
        *(uint4*)&sQh[r * AT_SD + c] = *(const uint4*)(Qh + src);
        *(uint4*)&sQl[r * AT_SD + c] = *(const uint4*)(Ql + src);
    }

    // o[2*dtile + u] accumulates dh columns [dtile*16 + u*8, +8)
    float o[16][4];
    #pragma unroll
    for (int nf = 0; nf < 16; nf++)
        #pragma unroll
        for (int c = 0; c < 4; c++) o[nf][c] = 0.0f;
    float mr0 = -INFINITY, mr1 = -INFINITY, lr0 = 0.0f, lr1 = 0.0f;

    const uint32_t cQh = (uint32_t)__cvta_generic_to_shared(sQh);
    const uint32_t cQl = (uint32_t)__cvta_generic_to_shared(sQl);
    const uint32_t cKh = (uint32_t)__cvta_generic_to_shared(sKh);
    const uint32_t cKl = (uint32_t)__cvta_generic_to_shared(sKl);
    const uint32_t cVh = (uint32_t)__cvta_generic_to_shared(sVh);
    const uint32_t cVl = (uint32_t)__cvta_generic_to_shared(sVl);
    const uint32_t aoff  = (uint32_t)(((warp * 16 + (lane & 15)) * AT_SD + ((lane >> 4) * 8)) * 2);
    const uint32_t boffK = (uint32_t)((((lane & 7) + ((lane >> 4) * 8)) * AT_SD
                                      + (((lane >> 3) & 1) * 8)) * 2);
    // trans V load: row = kv0 + (lane&15), col = (lane>>4)*8  (within dh tile)
    const uint32_t boffVt = (uint32_t)(((lane & 15) * AT_SD + ((lane >> 4) * 8)) * 2);

    for (int kb = 0; kb <= qb; kb++) {
        __syncthreads();   // prior iter's smem reads done (also covers Q store, iter 0)
        for (int i = tid; i < 64 * 16; i += 128) {
            int r = i >> 4, c = (i & 15) << 3;
            size_t src = base + (size_t)(kb * 64 + r) * D_MODEL + c;
            *(uint4*)&sKh[r * AT_SD + c] = *(const uint4*)(Kh + src);
            *(uint4*)&sKl[r * AT_SD + c] = *(const uint4*)(Kl + src);
            *(uint4*)&sVh[r * AT_SD + c] = *(const uint4*)(Vh + src);
            *(uint4*)&sVl[r * AT_SD + c] = *(const uint4*)(Vl + src);
        }
        __syncthreads();

        // ---- S = Q K^T (16 x 64 per warp), bf16x3 ----
        float s[8][4];
        #pragma unroll
        for (int tt = 0; tt < 8; tt++)
            #pragma unroll
            for (int c = 0; c < 4; c++) s[tt][c] = 0.0f;

        #pragma unroll
        for (int ks = 0; ks < 8; ks++) {
            uint32_t qh[4], ql[4];
            LDSM_X4(qh[0], qh[1], qh[2], qh[3], cQh + aoff + ks * 32);
            LDSM_X4(ql[0], ql[1], ql[2], ql[3], cQl + aoff + ks * 32);
            #pragma unroll
            for (int p = 0; p < 4; p++) {
                uint32_t kh[4], kl[4];
                uint32_t bd = boffK + p * (16 * AT_SD * 2) + ks * 32;
                LDSM_X4(kh[0], kh[1], kh[2], kh[3], cKh + bd);
                LDSM_X4(kl[0], kl[1], kl[2], kl[3], cKl + bd);
                uint32_t bh0[2] = {kh[0], kh[1]}, bh1[2] = {kh[2], kh[3]};
                uint32_t bl0[2] = {kl[0], kl[1]}, bl1[2] = {kl[2], kl[3]};
                MMA16816(s[2*p],     qh, bh0);
                MMA16816(s[2*p],     ql, bh0);
                MMA16816(s[2*p],     qh, bl0);
                MMA16816(s[2*p + 1], qh, bh1);
                MMA16816(s[2*p + 1], ql, bh1);
                MMA16816(s[2*p + 1], qh, bl1);
            }
        }

        if (kb == qb) {
            int r0 = warp * 16 + g, r1 = r0 + 8;
            #pragma unroll
            for (int tt = 0; tt < 8; tt++) {
                int c0 = tt * 8 + tq * 2;
                if (c0     > r0) s[tt][0] = -INFINITY;
                if (c0 + 1 > r0) s[tt][1] = -INFINITY;
                if (c0     > r1) s[tt][2] = -INFINITY;
                if (c0 + 1 > r1) s[tt][3] = -INFINITY;
            }
        }

        // ---- online softmax (rows g, g+8) ----
        float mx0 = -INFINITY, mx1 = -INFINITY;
        #pragma unroll
        for (int tt = 0; tt < 8; tt++) {
            mx0 = fmaxf(mx0, fmaxf(s[tt][0], s[tt][1]));
            mx1 = fmaxf(mx1, fmaxf(s[tt][2], s[tt][3]));
        }
        mx0 = fmaxf(mx0, __shfl_xor_sync(0xffffffffu, mx0, 1));
        mx0 = fmaxf(mx0, __shfl_xor_sync(0xffffffffu, mx0, 2));
        mx1 = fmaxf(mx1, __shfl_xor_sync(0xffffffffu, mx1, 1));
        mx1 = fmaxf(mx1, __shfl_xor_sync(0xffffffffu, mx1, 2));

        float mn0 = fmaxf(mr0, mx0), mn1 = fmaxf(mr1, mx1);
        float al0 = __expf(mr0 - mn0), al1 = __expf(mr1 - mn1);
        float sum0 = 0.0f, sum1 = 0.0f;
        #pragma unroll
        for (int tt = 0; tt < 8; tt++) {
            s[tt][0] = __expf(s[tt][0] - mn0);
            s[tt][1] = __expf(s[tt][1] - mn0);
            s[tt][2] = __expf(s[tt][2] - mn1);
            s[tt][3] = __expf(s[tt][3] - mn1);
            sum0 += s[tt][0] + s[tt][1];
            sum1 += s[tt][2] + s[tt][3];
        }
        sum0 += __shfl_xor_sync(0xffffffffu, sum0, 1);
        sum0 += __shfl_xor_sync(0xffffffffu, sum0, 2);
        sum1 += __shfl_xor_sync(0xffffffffu, sum1, 1);
        sum1 += __shfl_xor_sync(0xffffffffu, sum1, 2);
        lr0 = lr0 * al0 + sum0;
        lr1 = lr1 * al1 + sum1;
        mr0 = mn0;
        mr1 = mn1;
        #pragma unroll
        for (int nf = 0; nf < 16; nf++) {
            o[nf][0] *= al0; o[nf][1] *= al0;
            o[nf][2] *= al1; o[nf][3] *= al1;
        }

        // ---- O += P V  (P from registers; V via trans ldmatrix) ----
        // j: kv slab of 16 (A operand k). dtile: dh slab of 16 (two n8 tiles).
        #pragma unroll
        for (int j = 0; j < 4; j++) {
            uint32_t ph[4], pl[4];
            split2pack(s[2*j][0],     s[2*j][1],     ph[0], pl[0]);
            split2pack(s[2*j][2],     s[2*j][3],     ph[1], pl[1]);
            split2pack(s[2*j + 1][0], s[2*j + 1][1], ph[2], pl[2]);
            split2pack(s[2*j + 1][2], s[2*j + 1][3], ph[3], pl[3]);
            #pragma unroll
            for (int dtile = 0; dtile < 8; dtile++) {
                uint32_t vh4[4], vl4[4];
                uint32_t bd = boffVt + (uint32_t)((j * 16 * AT_SD + dtile * 16) * 2);
                LDSM_X4_T(vh4[0], vh4[1], vh4[2], vh4[3], cVh + bd);
                LDSM_X4_T(vl4[0], vl4[1], vl4[2], vl4[3], cVl + bd);
                uint32_t bh0[2] = {vh4[0], vh4[1]}, bh1[2] = {vh4[2], vh4[3]};
                uint32_t bl0[2] = {vl4[0], vl4[1]}, bl1[2] = {vl4[2], vl4[3]};
                MMA16816(o[2*dtile],     ph, bh0);
                MMA16816(o[2*dtile],     pl, bh0);
                MMA16816(o[2*dtile],     ph, bl0);
                MMA16816(o[2*dtile + 1], ph, bh1);
                MMA16816(o[2*dtile + 1], pl, bh1);
                MMA16816(o[2*dtile + 1], ph, bl1);
            }
        }
    }

    // epilogue: o[2*dtile + u] -> dh cols dtile*16 + u*8 + tq*2
    float inv0 = 1.0f / lr0, inv1 = 1.0f / lr1;
    int r0 = qb * 64 + warp * 16 + g;
    #pragma unroll
    for (int dtile = 0; dtile < 8; dtile++) {
        #pragma unroll
        for (int u = 0; u < 2; u++) {
            int nf = 2 * dtile + u;
            int c = dtile * 16 + u * 8 + tq * 2;
            *(float2*)&O[base + (size_t)r0 * D_MODEL + c] =
                make_float2(o[nf][0] * inv0, o[nf][1] * inv0);
            *(float2*)&O[base + (size_t)(r0 + 8) * D_MODEL + c] =
                make_float2(o[nf][2] * inv1, o[nf][3] * inv1);
        }
    }
}

// ---------------- launch ----------------------------------------------------
extern "C" void kernel_launch(void* const* d_in, const int* in_sizes, int n_in,
                              void* d_out, int out_size)
{
    (void)in_sizes; (void)n_in; (void)out_size;
    const float* hidden = (const float*)d_in[0];
    const float* Wq = (const float*)d_in[3];
    const float* Wk = (const float*)d_in[4];
    const float* Wv = (const float*)d_in[5];
    const float* Wo = (const float*)d_in[6];
    float* out = (float*)d_out;

    float *Qp, *Kp, *Vp, *Op;
    __nv_bfloat16 *Ahp, *Alp, *Bhp, *Blp;
    __nv_bfloat16 *Qhp, *Qlp, *Khp, *Klp, *Vhp, *Vlp;
    cudaGetSymbolAddress((void**)&Qp, g_Q);
    cudaGetSymbolAddress((void**)&Kp, g_K);
    cudaGetSymbolAddress((void**)&Vp, g_V);
    cudaGetSymbolAddress((void**)&Op, g_O);
    cudaGetSymbolAddress((void**)&Ahp, g_Ah);
    cudaGetSymbolAddress((void**)&Alp, g_Al);
    cudaGetSymbolAddress((void**)&Bhp, g_Bh);
    cudaGetSymbolAddress((void**)&Blp, g_Bl);
    cudaGetSymbolAddress((void**)&Qhp, g_Qh);
    cudaGetSymbolAddress((void**)&Qlp, g_Ql);
    cudaGetSymbolAddress((void**)&Khp, g_Kh);
    cudaGetSymbolAddress((void**)&Klp, g_Kl);
    cudaGetSymbolAddress((void**)&Vhp, g_Vh);
    cudaGetSymbolAddress((void**)&Vlp, g_Vl);

    rope_table_kernel<<<(S_LEN * 64 + 255) / 256, 256>>>();

    int n2 = TOKENS * D_MODEL / 2;
    split_kernel<<<(n2 + 255) / 256, 256>>>(hidden, Ahp, Alp, n2);

    dim3 tgrid(D_MODEL / 32, D_MODEL / 32);
    dim3 tblk(32, 8);
    dim3 ggrid(D_MODEL / TBN, TOKENS / TBM);

    cudaFuncSetAttribute(gemm_bf16x3_kernel,
                         cudaFuncAttributeMaxDynamicSharedMemorySize, GEMM_SMEM);

    tsplit_kernel<<<tgrid, tblk>>>(Wq, Bhp, Blp);
    gemm_bf16x3_kernel<<<ggrid, 256, GEMM_SMEM>>>(Ahp, Alp, Bhp, Blp, Qp);
    tsplit_kernel<<<tgrid, tblk>>>(Wk, Bhp, Blp);
    gemm_bf16x3_kernel<<<ggrid, 256, GEMM_SMEM>>>(Ahp, Alp, Bhp, Blp, Kp);
    tsplit_kernel<<<tgrid, tblk>>>(Wv, Bhp, Blp);
    gemm_bf16x3_kernel<<<ggrid, 256, GEMM_SMEM>>>(Ahp, Alp, Bhp, Blp, Vp);

    int nrope = TOKENS * NH * 64;
    rope_split_kernel<<<(nrope + 255) / 256, 256>>>(Qp, Qhp, Qlp, 0.08838834764831845f);
    rope_split_kernel<<<(nrope + 255) / 256, 256>>>(Kp, Khp, Klp, 1.0f);
    split_kernel<<<(n2 + 255) / 256, 256>>>(Vp, Vhp, Vlp, n2);

    cudaFuncSetAttribute(attn_tc_kernel,
                         cudaFuncAttributeMaxDynamicSharedMemorySize, ATT_SMEM);
    attn_tc_kernel<<<dim3(S_LEN / 64, NH, BATCH), 128, ATT_SMEM>>>(
        Qhp, Qlp, Khp, Klp, Vhp, Vlp, Op);

    split_kernel<<<(n2 + 255) / 256, 256>>>(Op, Ahp, Alp, n2);
    tsplit_kernel<<<tgrid, tblk>>>(Wo, Bhp, Blp);
    gemm_bf16x3_kernel<<<ggrid, 256, GEMM_SMEM>>>(Ahp, Alp, Bhp, Blp, out);
}